// round 4
// baseline (speedup 1.0000x reference)
#include <cuda_runtime.h>
#include <math.h>
#include <stdint.h>

// Peephole LSTM  B=256, T=512, I=H=O=1024
// Round 4: same architecture as round 3, with the B-prefetch address bug fixed.
// 4 graph nodes, TF32 mma.sync, persistent recurrent kernel.

#define BATCH 256
#define TT    512
#define HID   1024
#define KD    1024
#define NG    4096
#define NCTA  128

// ---------------- device globals (small; allocation-free scratch) ----------------
__device__ float g_Wxp[(size_t)NG * KD];            // 16 MB packed x2h weight
__device__ float g_Whp[(size_t)NG * KD];            // 16 MB packed h2h weight
__device__ float g_biasp[NG];                       // packed bx+bh
__device__ float g_h[2][BATCH * HID];               // double-buffered hidden
__device__ float g_c[BATCH * HID];                  // cell state
__device__ unsigned g_bar_arrive;
__device__ volatile unsigned g_bar_gen;

// ---------------- helpers ----------------
__device__ __forceinline__ uint32_t f2t(float f) {
    uint32_t u;
    asm("cvt.rna.tf32.f32 %0, %1;" : "=r"(u) : "f"(f));
    return u;
}

__device__ __forceinline__ void mma_m16n8k8(float d[4], const uint32_t a[4], const uint32_t b[2]) {
    asm volatile(
        "mma.sync.aligned.m16n8k8.row.col.f32.tf32.tf32.f32 "
        "{%0,%1,%2,%3}, {%4,%5,%6,%7}, {%8,%9}, {%0,%1,%2,%3};"
        : "+f"(d[0]), "+f"(d[1]), "+f"(d[2]), "+f"(d[3])
        : "r"(a[0]), "r"(a[1]), "r"(a[2]), "r"(a[3]), "r"(b[0]), "r"(b[1]));
}

__device__ __forceinline__ float sigf(float x) { return 1.f / (1.f + __expf(-x)); }

// K-loop over KD with 32-wide chunks. CTA tile = MR x NR. 256 threads.
// Warp computes a 32x32 tile at (warp_m, warp_n). Accumulates into acc.
template <int MR, int NR, bool ACG>
__device__ __forceinline__ void ktile_loop(
    const float* __restrict__ Ag, size_t lda,
    const float* __restrict__ Bg, size_t ldb,
    uint32_t* As, uint32_t* Bs,
    int warp_m, int warp_n,
    float acc[2][4][4])
{
    constexpr int AV = MR * 32 / (4 * 256);  // float4 loads per thread for A
    constexpr int BV = NR * 32 / (4 * 256);
    const int tid = threadIdx.x;
    const int lane = tid & 31;

    float4 ar[AV], br[BV];

    // prefetch chunk 0
#pragma unroll
    for (int i = 0; i < AV; i++) {
        int idx = i * 256 + tid, r = idx >> 3, kq = idx & 7;
        const float4* p = (const float4*)(Ag + (size_t)r * lda + kq * 4);
        ar[i] = ACG ? __ldcg(p) : __ldg(p);
    }
#pragma unroll
    for (int i = 0; i < BV; i++) {
        int idx = i * 256 + tid, r = idx >> 3, kq = idx & 7;
        br[i] = __ldg((const float4*)(Bg + (size_t)r * ldb + kq * 4));
    }

    for (int kt = 0; kt < KD / 32; kt++) {
        // regs (chunk kt) -> smem, tf32-converted
#pragma unroll
        for (int i = 0; i < AV; i++) {
            int idx = i * 256 + tid, r = idx >> 3, kq = idx & 7;
            *(uint4*)(As + r * 36 + kq * 4) =
                make_uint4(f2t(ar[i].x), f2t(ar[i].y), f2t(ar[i].z), f2t(ar[i].w));
        }
#pragma unroll
        for (int i = 0; i < BV; i++) {
            int idx = i * 256 + tid, r = idx >> 3, kq = idx & 7;
            *(uint4*)(Bs + r * 36 + kq * 4) =
                make_uint4(f2t(br[i].x), f2t(br[i].y), f2t(br[i].z), f2t(br[i].w));
        }
        __syncthreads();

        // prefetch chunk kt+1
        if (kt + 1 < KD / 32) {
            int koff = (kt + 1) * 32;
#pragma unroll
            for (int i = 0; i < AV; i++) {
                int idx = i * 256 + tid, r = idx >> 3, kq = idx & 7;
                const float4* p = (const float4*)(Ag + (size_t)r * lda + koff + kq * 4);
                ar[i] = ACG ? __ldcg(p) : __ldg(p);
            }
#pragma unroll
            for (int i = 0; i < BV; i++) {
                int idx = i * 256 + tid, r = idx >> 3, kq = idx & 7;
                br[i] = __ldg((const float4*)(Bg + (size_t)r * ldb + koff + kq * 4));
            }
        }

        // compute on chunk kt
#pragma unroll
        for (int kk = 0; kk < 32; kk += 8) {
            uint32_t af[2][4];
#pragma unroll
            for (int mt = 0; mt < 2; mt++) {
                const uint32_t* ap = As + (warp_m + mt * 16 + (lane >> 2)) * 36 + kk + (lane & 3);
                af[mt][0] = ap[0];
                af[mt][1] = ap[8 * 36];
                af[mt][2] = ap[4];
                af[mt][3] = ap[8 * 36 + 4];
            }
            uint32_t bf[4][2];
#pragma unroll
            for (int nt = 0; nt < 4; nt++) {
                const uint32_t* bp = Bs + (warp_n + nt * 8 + (lane >> 2)) * 36 + kk + (lane & 3);
                bf[nt][0] = bp[0];
                bf[nt][1] = bp[4];
            }
#pragma unroll
            for (int mt = 0; mt < 2; mt++)
#pragma unroll
                for (int nt = 0; nt < 4; nt++)
                    mma_m16n8k8(acc[mt][nt], af[mt], bf[nt]);
        }
        __syncthreads();
    }
}

// ---------------- pack weights/biases into gate-interleaved layout ----------------
// packed row n' = j*4 + g  for original row n = g*1024 + j
__global__ __launch_bounds__(256) void pack_kernel(
    const float* __restrict__ Wx, const float* __restrict__ Wh,
    const float* __restrict__ bx, const float* __restrict__ bh)
{
    int n = blockIdx.x;                 // 0..4095
    int g = n >> 10, j = n & 1023;
    int np = j * 4 + g;
    const float4* sx = (const float4*)(Wx + (size_t)n * KD);
    const float4* sh = (const float4*)(Wh + (size_t)n * KD);
    float4* dx = (float4*)(g_Wxp + (size_t)np * KD);
    float4* dh = (float4*)(g_Whp + (size_t)np * KD);
    dx[threadIdx.x] = sx[threadIdx.x];
    dh[threadIdx.x] = sh[threadIdx.x];
    if (threadIdx.x == 0) g_biasp[np] = bx[n] + bh[n];
}

__global__ void init_kernel()
{
    int idx = blockIdx.x * blockDim.x + threadIdx.x;   // 0..262143
    g_h[0][idx] = 0.f;
    g_c[idx] = 0.f;
    if (idx == 0) { g_bar_arrive = 0; g_bar_gen = 0; }
}

// ---------------- persistent recurrent kernel ----------------
__device__ __forceinline__ void gbar()
{
    __syncthreads();
    if (threadIdx.x == 0) {
        __threadfence();
        unsigned g = g_bar_gen;
        unsigned a = atomicAdd(&g_bar_arrive, 1);
        if (a == NCTA - 1) {
            g_bar_arrive = 0;
            __threadfence();
            g_bar_gen = g + 1;
        } else {
            while (g_bar_gen == g) __nanosleep(64);
        }
    }
    __syncthreads();
}

__global__ __launch_bounds__(256, 1) void lstm_steps(
    const float* __restrict__ x,
    const float* __restrict__ c2c)
{
    __shared__ __align__(16) uint32_t As[64 * 36];
    __shared__ __align__(16) uint32_t Bs[128 * 36];
    int cta = blockIdx.x;
    int rb = (cta >> 5) * 64;           // batch-row base (64 rows)
    int nb = (cta & 31) * 128;          // packed-col base (128 cols)
    int tid = threadIdx.x, wid = tid >> 5, lane = tid & 31;
    int wm = (wid >> 2) * 32, wn = (wid & 3) * 32;   // 2x4 warps

    for (int t = 0; t < TT; t++) {
        const float* hp = g_h[t & 1];
        float* hn = g_h[(t + 1) & 1];

        float acc[2][4][4];
#pragma unroll
        for (int a = 0; a < 2; a++)
#pragma unroll
            for (int b = 0; b < 4; b++)
#pragma unroll
                for (int c = 0; c < 4; c++) acc[a][b][c] = 0.f;

        // gates = x_t @ Wxp^T   (row b of x_t at x + (b*TT + t)*KD, lda = TT*KD)
        ktile_loop<64, 128, false>(x + ((size_t)rb * TT + t) * KD, (size_t)TT * KD,
                                   g_Wxp + (size_t)nb * KD, KD,
                                   As, Bs, wm, wn, acc);
        //       += h @ Whp^T
        ktile_loop<64, 128, true>(hp + (size_t)rb * HID, HID,
                                  g_Whp + (size_t)nb * KD, KD,
                                  As, Bs, wm, wn, acc);

        // fused peephole gate update
#pragma unroll
        for (int mt = 0; mt < 2; mt++)
#pragma unroll
            for (int nt = 0; nt < 4; nt++) {
                int row0 = rb + wm + mt * 16 + (lane >> 2);
                int col = nb + wn + nt * 8 + 2 * (lane & 3);
                float b0 = __ldg(g_biasp + col);
                float b1 = __ldg(g_biasp + col + 1);
                float p0 = acc[mt][nt][0] + b0;   // (row0, col)
                float p1 = acc[mt][nt][1] + b1;   // (row0, col+1)
                float p2 = acc[mt][nt][2] + b0;   // (row0+8, col)
                float p3 = acc[mt][nt][3] + b1;
                float q0 = __shfl_xor_sync(0xffffffffu, p0, 1);
                float q1 = __shfl_xor_sync(0xffffffffu, p1, 1);
                float q2 = __shfl_xor_sync(0xffffffffu, p2, 1);
                float q3 = __shfl_xor_sync(0xffffffffu, p3, 1);
                if (!(lane & 1)) {
                    // even lane holds (i,f) at cols 4j, 4j+1; partner delivered (g,o)
                    int j = col >> 2;
                    float ciw = __ldg(c2c + j);
                    float cfw = __ldg(c2c + 1024 + j);
                    float cow = __ldg(c2c + 2048 + j);
                    {
                        float cold = g_c[row0 * HID + j];
                        float ig = sigf(p0 + ciw * cold);
                        float fg = sigf(p1 + cfw * cold);
                        float cn = fg * cold + ig * tanhf(q0);
                        float og = sigf(q1 + cow * cn);
                        g_c[row0 * HID + j] = cn;
                        hn[row0 * HID + j] = og * tanhf(cn);
                    }
                    {
                        int row1 = row0 + 8;
                        float cold = g_c[row1 * HID + j];
                        float ig = sigf(p2 + ciw * cold);
                        float fg = sigf(p3 + cfw * cold);
                        float cn = fg * cold + ig * tanhf(q2);
                        float og = sigf(q3 + cow * cn);
                        g_c[row1 * HID + j] = cn;
                        hn[row1 * HID + j] = og * tanhf(cn);
                    }
                }
            }
        gbar();
    }
}

// ---------------- final fc: out = h @ Wfc^T + bfc ----------------
__global__ __launch_bounds__(256) void fc_gemm(
    const float* __restrict__ Wfc, const float* __restrict__ bfc,
    float* __restrict__ out)
{
    __shared__ __align__(16) uint32_t As[128 * 36];
    __shared__ __align__(16) uint32_t Bs[64 * 36];
    int mb = blockIdx.y * 128;
    int nb = blockIdx.x * 64;
    int wid = threadIdx.x >> 5, lane = threadIdx.x & 31;
    int wm = (wid >> 1) * 32, wn = (wid & 1) * 32;

    float acc[2][4][4];
#pragma unroll
    for (int a = 0; a < 2; a++)
#pragma unroll
        for (int b = 0; b < 4; b++)
#pragma unroll
            for (int c = 0; c < 4; c++) acc[a][b][c] = 0.f;

    // final h lives in g_h[0] (T=512 even)
    ktile_loop<128, 64, true>(g_h[0] + (size_t)mb * HID, HID,
                              Wfc + (size_t)nb * KD, KD,
                              As, Bs, wm, wn, acc);

#pragma unroll
    for (int mt = 0; mt < 2; mt++)
#pragma unroll
        for (int nt = 0; nt < 4; nt++) {
            int col = nb + wn + nt * 8 + 2 * (lane & 3);
            float b0 = __ldg(bfc + col), b1 = __ldg(bfc + col + 1);
#pragma unroll
            for (int rh = 0; rh < 2; rh++) {
                int row = mb + wm + mt * 16 + (lane >> 2) + rh * 8;
                float2 v;
                v.x = acc[mt][nt][rh * 2 + 0] + b0;
                v.y = acc[mt][nt][rh * 2 + 1] + b1;
                *(float2*)(out + (size_t)row * 1024 + col) = v;
            }
        }
}

// ---------------- launch ----------------
extern "C" void kernel_launch(void* const* d_in, const int* in_sizes, int n_in,
                              void* d_out, int out_size)
{
    const float* x   = (const float*)d_in[0];
    const float* Wx  = (const float*)d_in[1];
    const float* bx  = (const float*)d_in[2];
    const float* Wh  = (const float*)d_in[3];
    const float* bh  = (const float*)d_in[4];
    const float* c2c = (const float*)d_in[5];
    const float* Wfc = (const float*)d_in[6];
    const float* bfc = (const float*)d_in[7];
    float* out = (float*)d_out;

    pack_kernel<<<4096, 256>>>(Wx, Wh, bx, bh);
    init_kernel<<<1024, 256>>>();
    lstm_steps<<<NCTA, 256>>>(x, c2c);
    fc_gemm<<<dim3(16, 2), 256>>>(Wfc, bfc, out);
}

// round 5
// speedup vs baseline: 1.0019x; 1.0019x over previous
#include <cuda_runtime.h>
#include <math.h>
#include <stdint.h>

// Peephole LSTM  B=256, T=512, I=H=O=1024
// Round 4: same architecture as round 3, with the B-prefetch address bug fixed.
// 4 graph nodes, TF32 mma.sync, persistent recurrent kernel.

#define BATCH 256
#define TT    512
#define HID   1024
#define KD    1024
#define NG    4096
#define NCTA  128

// ---------------- device globals (small; allocation-free scratch) ----------------
__device__ float g_Wxp[(size_t)NG * KD];            // 16 MB packed x2h weight
__device__ float g_Whp[(size_t)NG * KD];            // 16 MB packed h2h weight
__device__ float g_biasp[NG];                       // packed bx+bh
__device__ float g_h[2][BATCH * HID];               // double-buffered hidden
__device__ float g_c[BATCH * HID];                  // cell state
__device__ unsigned g_bar_arrive;
__device__ volatile unsigned g_bar_gen;

// ---------------- helpers ----------------
__device__ __forceinline__ uint32_t f2t(float f) {
    uint32_t u;
    asm("cvt.rna.tf32.f32 %0, %1;" : "=r"(u) : "f"(f));
    return u;
}

__device__ __forceinline__ void mma_m16n8k8(float d[4], const uint32_t a[4], const uint32_t b[2]) {
    asm volatile(
        "mma.sync.aligned.m16n8k8.row.col.f32.tf32.tf32.f32 "
        "{%0,%1,%2,%3}, {%4,%5,%6,%7}, {%8,%9}, {%0,%1,%2,%3};"
        : "+f"(d[0]), "+f"(d[1]), "+f"(d[2]), "+f"(d[3])
        : "r"(a[0]), "r"(a[1]), "r"(a[2]), "r"(a[3]), "r"(b[0]), "r"(b[1]));
}

__device__ __forceinline__ float sigf(float x) { return 1.f / (1.f + __expf(-x)); }

// K-loop over KD with 32-wide chunks. CTA tile = MR x NR. 256 threads.
// Warp computes a 32x32 tile at (warp_m, warp_n). Accumulates into acc.
template <int MR, int NR, bool ACG>
__device__ __forceinline__ void ktile_loop(
    const float* __restrict__ Ag, size_t lda,
    const float* __restrict__ Bg, size_t ldb,
    uint32_t* As, uint32_t* Bs,
    int warp_m, int warp_n,
    float acc[2][4][4])
{
    constexpr int AV = MR * 32 / (4 * 256);  // float4 loads per thread for A
    constexpr int BV = NR * 32 / (4 * 256);
    const int tid = threadIdx.x;
    const int lane = tid & 31;

    float4 ar[AV], br[BV];

    // prefetch chunk 0
#pragma unroll
    for (int i = 0; i < AV; i++) {
        int idx = i * 256 + tid, r = idx >> 3, kq = idx & 7;
        const float4* p = (const float4*)(Ag + (size_t)r * lda + kq * 4);
        ar[i] = ACG ? __ldcg(p) : __ldg(p);
    }
#pragma unroll
    for (int i = 0; i < BV; i++) {
        int idx = i * 256 + tid, r = idx >> 3, kq = idx & 7;
        br[i] = __ldg((const float4*)(Bg + (size_t)r * ldb + kq * 4));
    }

    for (int kt = 0; kt < KD / 32; kt++) {
        // regs (chunk kt) -> smem, tf32-converted
#pragma unroll
        for (int i = 0; i < AV; i++) {
            int idx = i * 256 + tid, r = idx >> 3, kq = idx & 7;
            *(uint4*)(As + r * 36 + kq * 4) =
                make_uint4(f2t(ar[i].x), f2t(ar[i].y), f2t(ar[i].z), f2t(ar[i].w));
        }
#pragma unroll
        for (int i = 0; i < BV; i++) {
            int idx = i * 256 + tid, r = idx >> 3, kq = idx & 7;
            *(uint4*)(Bs + r * 36 + kq * 4) =
                make_uint4(f2t(br[i].x), f2t(br[i].y), f2t(br[i].z), f2t(br[i].w));
        }
        __syncthreads();

        // prefetch chunk kt+1
        if (kt + 1 < KD / 32) {
            int koff = (kt + 1) * 32;
#pragma unroll
            for (int i = 0; i < AV; i++) {
                int idx = i * 256 + tid, r = idx >> 3, kq = idx & 7;
                const float4* p = (const float4*)(Ag + (size_t)r * lda + koff + kq * 4);
                ar[i] = ACG ? __ldcg(p) : __ldg(p);
            }
#pragma unroll
            for (int i = 0; i < BV; i++) {
                int idx = i * 256 + tid, r = idx >> 3, kq = idx & 7;
                br[i] = __ldg((const float4*)(Bg + (size_t)r * ldb + koff + kq * 4));
            }
        }

        // compute on chunk kt
#pragma unroll
        for (int kk = 0; kk < 32; kk += 8) {
            uint32_t af[2][4];
#pragma unroll
            for (int mt = 0; mt < 2; mt++) {
                const uint32_t* ap = As + (warp_m + mt * 16 + (lane >> 2)) * 36 + kk + (lane & 3);
                af[mt][0] = ap[0];
                af[mt][1] = ap[8 * 36];
                af[mt][2] = ap[4];
                af[mt][3] = ap[8 * 36 + 4];
            }
            uint32_t bf[4][2];
#pragma unroll
            for (int nt = 0; nt < 4; nt++) {
                const uint32_t* bp = Bs + (warp_n + nt * 8 + (lane >> 2)) * 36 + kk + (lane & 3);
                bf[nt][0] = bp[0];
                bf[nt][1] = bp[4];
            }
#pragma unroll
            for (int mt = 0; mt < 2; mt++)
#pragma unroll
                for (int nt = 0; nt < 4; nt++)
                    mma_m16n8k8(acc[mt][nt], af[mt], bf[nt]);
        }
        __syncthreads();
    }
}

// ---------------- pack weights/biases into gate-interleaved layout ----------------
// packed row n' = j*4 + g  for original row n = g*1024 + j
__global__ __launch_bounds__(256) void pack_kernel(
    const float* __restrict__ Wx, const float* __restrict__ Wh,
    const float* __restrict__ bx, const float* __restrict__ bh)
{
    int n = blockIdx.x;                 // 0..4095
    int g = n >> 10, j = n & 1023;
    int np = j * 4 + g;
    const float4* sx = (const float4*)(Wx + (size_t)n * KD);
    const float4* sh = (const float4*)(Wh + (size_t)n * KD);
    float4* dx = (float4*)(g_Wxp + (size_t)np * KD);
    float4* dh = (float4*)(g_Whp + (size_t)np * KD);
    dx[threadIdx.x] = sx[threadIdx.x];
    dh[threadIdx.x] = sh[threadIdx.x];
    if (threadIdx.x == 0) g_biasp[np] = bx[n] + bh[n];
}

__global__ void init_kernel()
{
    int idx = blockIdx.x * blockDim.x + threadIdx.x;   // 0..262143
    g_h[0][idx] = 0.f;
    g_c[idx] = 0.f;
    if (idx == 0) { g_bar_arrive = 0; g_bar_gen = 0; }
}

// ---------------- persistent recurrent kernel ----------------
__device__ __forceinline__ void gbar()
{
    __syncthreads();
    if (threadIdx.x == 0) {
        __threadfence();
        unsigned g = g_bar_gen;
        unsigned a = atomicAdd(&g_bar_arrive, 1);
        if (a == NCTA - 1) {
            g_bar_arrive = 0;
            __threadfence();
            g_bar_gen = g + 1;
        } else {
            while (g_bar_gen == g) __nanosleep(64);
        }
    }
    __syncthreads();
}

__global__ __launch_bounds__(256, 1) void lstm_steps(
    const float* __restrict__ x,
    const float* __restrict__ c2c)
{
    __shared__ __align__(16) uint32_t As[64 * 36];
    __shared__ __align__(16) uint32_t Bs[128 * 36];
    int cta = blockIdx.x;
    int rb = (cta >> 5) * 64;           // batch-row base (64 rows)
    int nb = (cta & 31) * 128;          // packed-col base (128 cols)
    int tid = threadIdx.x, wid = tid >> 5, lane = tid & 31;
    int wm = (wid >> 2) * 32, wn = (wid & 3) * 32;   // 2x4 warps

    for (int t = 0; t < TT; t++) {
        const float* hp = g_h[t & 1];
        float* hn = g_h[(t + 1) & 1];

        float acc[2][4][4];
#pragma unroll
        for (int a = 0; a < 2; a++)
#pragma unroll
            for (int b = 0; b < 4; b++)
#pragma unroll
                for (int c = 0; c < 4; c++) acc[a][b][c] = 0.f;

        // gates = x_t @ Wxp^T   (row b of x_t at x + (b*TT + t)*KD, lda = TT*KD)
        ktile_loop<64, 128, false>(x + ((size_t)rb * TT + t) * KD, (size_t)TT * KD,
                                   g_Wxp + (size_t)nb * KD, KD,
                                   As, Bs, wm, wn, acc);
        //       += h @ Whp^T
        ktile_loop<64, 128, true>(hp + (size_t)rb * HID, HID,
                                  g_Whp + (size_t)nb * KD, KD,
                                  As, Bs, wm, wn, acc);

        // fused peephole gate update
#pragma unroll
        for (int mt = 0; mt < 2; mt++)
#pragma unroll
            for (int nt = 0; nt < 4; nt++) {
                int row0 = rb + wm + mt * 16 + (lane >> 2);
                int col = nb + wn + nt * 8 + 2 * (lane & 3);
                float b0 = __ldg(g_biasp + col);
                float b1 = __ldg(g_biasp + col + 1);
                float p0 = acc[mt][nt][0] + b0;   // (row0, col)
                float p1 = acc[mt][nt][1] + b1;   // (row0, col+1)
                float p2 = acc[mt][nt][2] + b0;   // (row0+8, col)
                float p3 = acc[mt][nt][3] + b1;
                float q0 = __shfl_xor_sync(0xffffffffu, p0, 1);
                float q1 = __shfl_xor_sync(0xffffffffu, p1, 1);
                float q2 = __shfl_xor_sync(0xffffffffu, p2, 1);
                float q3 = __shfl_xor_sync(0xffffffffu, p3, 1);
                if (!(lane & 1)) {
                    // even lane holds (i,f) at cols 4j, 4j+1; partner delivered (g,o)
                    int j = col >> 2;
                    float ciw = __ldg(c2c + j);
                    float cfw = __ldg(c2c + 1024 + j);
                    float cow = __ldg(c2c + 2048 + j);
                    {
                        float cold = g_c[row0 * HID + j];
                        float ig = sigf(p0 + ciw * cold);
                        float fg = sigf(p1 + cfw * cold);
                        float cn = fg * cold + ig * tanhf(q0);
                        float og = sigf(q1 + cow * cn);
                        g_c[row0 * HID + j] = cn;
                        hn[row0 * HID + j] = og * tanhf(cn);
                    }
                    {
                        int row1 = row0 + 8;
                        float cold = g_c[row1 * HID + j];
                        float ig = sigf(p2 + ciw * cold);
                        float fg = sigf(p3 + cfw * cold);
                        float cn = fg * cold + ig * tanhf(q2);
                        float og = sigf(q3 + cow * cn);
                        g_c[row1 * HID + j] = cn;
                        hn[row1 * HID + j] = og * tanhf(cn);
                    }
                }
            }
        gbar();
    }
}

// ---------------- final fc: out = h @ Wfc^T + bfc ----------------
__global__ __launch_bounds__(256) void fc_gemm(
    const float* __restrict__ Wfc, const float* __restrict__ bfc,
    float* __restrict__ out)
{
    __shared__ __align__(16) uint32_t As[128 * 36];
    __shared__ __align__(16) uint32_t Bs[64 * 36];
    int mb = blockIdx.y * 128;
    int nb = blockIdx.x * 64;
    int wid = threadIdx.x >> 5, lane = threadIdx.x & 31;
    int wm = (wid >> 1) * 32, wn = (wid & 1) * 32;

    float acc[2][4][4];
#pragma unroll
    for (int a = 0; a < 2; a++)
#pragma unroll
        for (int b = 0; b < 4; b++)
#pragma unroll
            for (int c = 0; c < 4; c++) acc[a][b][c] = 0.f;

    // final h lives in g_h[0] (T=512 even)
    ktile_loop<128, 64, true>(g_h[0] + (size_t)mb * HID, HID,
                              Wfc + (size_t)nb * KD, KD,
                              As, Bs, wm, wn, acc);

#pragma unroll
    for (int mt = 0; mt < 2; mt++)
#pragma unroll
        for (int nt = 0; nt < 4; nt++) {
            int col = nb + wn + nt * 8 + 2 * (lane & 3);
            float b0 = __ldg(bfc + col), b1 = __ldg(bfc + col + 1);
#pragma unroll
            for (int rh = 0; rh < 2; rh++) {
                int row = mb + wm + mt * 16 + (lane >> 2) + rh * 8;
                float2 v;
                v.x = acc[mt][nt][rh * 2 + 0] + b0;
                v.y = acc[mt][nt][rh * 2 + 1] + b1;
                *(float2*)(out + (size_t)row * 1024 + col) = v;
            }
        }
}

// ---------------- launch ----------------
extern "C" void kernel_launch(void* const* d_in, const int* in_sizes, int n_in,
                              void* d_out, int out_size)
{
    const float* x   = (const float*)d_in[0];
    const float* Wx  = (const float*)d_in[1];
    const float* bx  = (const float*)d_in[2];
    const float* Wh  = (const float*)d_in[3];
    const float* bh  = (const float*)d_in[4];
    const float* c2c = (const float*)d_in[5];
    const float* Wfc = (const float*)d_in[6];
    const float* bfc = (const float*)d_in[7];
    float* out = (float*)d_out;

    pack_kernel<<<4096, 256>>>(Wx, Wh, bx, bh);
    init_kernel<<<1024, 256>>>();
    lstm_steps<<<NCTA, 256>>>(x, c2c);
    fc_gemm<<<dim3(16, 2), 256>>>(Wfc, bfc, out);
}

// round 6
// speedup vs baseline: 1.0914x; 1.0893x over previous
#include <cuda_runtime.h>
#include <math.h>
#include <stdint.h>

// Peephole LSTM  B=256, T=512, I=H=O=1024
// Round 6: cp.async 3-stage pipeline, K-permuted operands, LDS.128 fragments,
// all tf32 rounding hoisted out of the recurrent loop. 5 graph nodes.

#define BATCH 256
#define TT    512
#define HID   1024
#define KD    1024
#define NG    4096
#define NCTA  128
#define LDSW  36
#define AS_W  (64 * LDSW)
#define BS_W  (128 * LDSW)
#define STG   (AS_W + BS_W)
#define SMEM_BYTES (3 * STG * 4)

// ---------------- device globals ----------------
__device__ float g_xp[(size_t)TT * BATCH * KD];   // 512 MB permuted/rounded x, [t][b][k]
__device__ float g_Wxp[(size_t)NG * KD];
__device__ float g_Whp[(size_t)NG * KD];
__device__ float g_Wfcp[(size_t)HID * KD];
__device__ float g_biasp[NG];
__device__ float g_hp[2][BATCH * HID];            // permuted/rounded hidden
__device__ float g_c[BATCH * HID];
__device__ unsigned g_bar_arrive;
__device__ volatile unsigned g_bar_gen;

// ---------------- helpers ----------------
__device__ __forceinline__ uint32_t f2t(float f) {
    uint32_t u; asm("cvt.rna.tf32.f32 %0, %1;" : "=r"(u) : "f"(f)); return u;
}
__device__ __forceinline__ void mma8(float d[4], const uint32_t a[4], const uint32_t b[2]) {
    asm volatile("mma.sync.aligned.m16n8k8.row.col.f32.tf32.tf32.f32 "
        "{%0,%1,%2,%3}, {%4,%5,%6,%7}, {%8,%9}, {%0,%1,%2,%3};"
        : "+f"(d[0]), "+f"(d[1]), "+f"(d[2]), "+f"(d[3])
        : "r"(a[0]), "r"(a[1]), "r"(a[2]), "r"(a[3]), "r"(b[0]), "r"(b[1]));
}
__device__ __forceinline__ float sigf(float x) { return 1.f / (1.f + __expf(-x)); }
__device__ __forceinline__ void cpa16(uint32_t dst, const void* src) {
    asm volatile("cp.async.cg.shared.global [%0], [%1], 16;" :: "r"(dst), "l"(src) : "memory");
}
#define CP_COMMIT() asm volatile("cp.async.commit_group;" ::: "memory")
#define CP_WAIT1()  asm volatile("cp.async.wait_group 1;"  ::: "memory")

// dest word w (within 32-chunk) <- source k: dest(k) = (k&3)*8 + ((k>>2)&7)
__device__ __forceinline__ int ksrc(int w) {            // inverse map
    return (w & ~31) + (((w) & 7) << 2) + (((w) >> 3) & 3);
}
__device__ __forceinline__ int pdst(int k) {
    return (k & ~31) + ((k & 3) << 3) + ((k >> 2) & 7);
}

// issue one 32-K chunk: A 64 rows + B 128 rows, stride KD, into stage.
__device__ __forceinline__ void issue_tile(uint32_t sbase, int stage,
    const float* __restrict__ Asrc, const float* __restrict__ Bsrc, int r8, int kq)
{
    uint32_t da = sbase + (uint32_t)(stage * STG * 4);
#pragma unroll
    for (int i = 0; i < 2; i++) { int r = i * 32 + r8;
        cpa16(da + ((r * LDSW + kq * 4) << 2), Asrc + (size_t)r * KD + kq * 4); }
    uint32_t db = da + AS_W * 4;
#pragma unroll
    for (int i = 0; i < 4; i++) { int r = i * 32 + r8;
        cpa16(db + ((r * LDSW + kq * 4) << 2), Bsrc + (size_t)r * KD + kq * 4); }
    CP_COMMIT();
}

__device__ __forceinline__ void compute_chunk(const uint32_t* __restrict__ st,
    const int aoff[4], const int boff[4], float acc[2][4][4])
{
    __align__(16) uint32_t a[4][8], b[4][8];
#pragma unroll
    for (int i = 0; i < 4; i++) {
        *(uint4*)&a[i][0] = *(const uint4*)(st + aoff[i]);
        *(uint4*)&a[i][4] = *(const uint4*)(st + aoff[i] + 4);
        *(uint4*)&b[i][0] = *(const uint4*)(st + boff[i]);
        *(uint4*)&b[i][4] = *(const uint4*)(st + boff[i] + 4);
    }
#pragma unroll
    for (int k4 = 0; k4 < 4; k4++)
#pragma unroll
        for (int mt = 0; mt < 2; mt++) {
            uint32_t af[4] = { a[mt*2][k4*2], a[mt*2+1][k4*2],
                               a[mt*2][k4*2+1], a[mt*2+1][k4*2+1] };
#pragma unroll
            for (int nt = 0; nt < 4; nt++) {
                uint32_t bf[2] = { b[nt][k4*2], b[nt][k4*2+1] };
                mma8(acc[mt][nt], af, bf);
            }
        }
}

// ---------------- pack kernels ----------------
__global__ __launch_bounds__(256) void pack_w(
    const float* __restrict__ Wx, const float* __restrict__ Wh,
    const float* __restrict__ bx, const float* __restrict__ bh,
    const float* __restrict__ Wfc)
{
    int n = blockIdx.x, w0 = threadIdx.x * 4;
    float v[4];
    if (n < NG) {
        int gg = n >> 10, j = n & 1023, np = j * 4 + gg;
        const float* s = Wx + (size_t)n * KD;
#pragma unroll
        for (int i = 0; i < 4; i++) v[i] = __uint_as_float(f2t(s[ksrc(w0 + i)]));
        *(float4*)(g_Wxp + (size_t)np * KD + w0) = make_float4(v[0], v[1], v[2], v[3]);
        s = Wh + (size_t)n * KD;
#pragma unroll
        for (int i = 0; i < 4; i++) v[i] = __uint_as_float(f2t(s[ksrc(w0 + i)]));
        *(float4*)(g_Whp + (size_t)np * KD + w0) = make_float4(v[0], v[1], v[2], v[3]);
        if (threadIdx.x == 0) g_biasp[np] = bx[n] + bh[n];
    } else {
        int m = n - NG;
        const float* s = Wfc + (size_t)m * KD;
#pragma unroll
        for (int i = 0; i < 4; i++) v[i] = __uint_as_float(f2t(s[ksrc(w0 + i)]));
        *(float4*)(g_Wfcp + (size_t)m * KD + w0) = make_float4(v[0], v[1], v[2], v[3]);
    }
}

__global__ __launch_bounds__(256) void pack_x(const float* __restrict__ x)
{
    int bt = blockIdx.x;                  // b*TT + t
    int b = bt >> 9, t = bt & 511;
    int w0 = threadIdx.x * 4;
    const float* s = x + (size_t)bt * KD;
    float v[4];
#pragma unroll
    for (int i = 0; i < 4; i++) v[i] = __uint_as_float(f2t(__ldg(s + ksrc(w0 + i))));
    *(float4*)(g_xp + ((size_t)t * BATCH + b) * KD + w0) = make_float4(v[0], v[1], v[2], v[3]);
}

__global__ void init_kernel()
{
    int idx = blockIdx.x * blockDim.x + threadIdx.x;
    g_hp[0][idx] = 0.f;
    g_c[idx] = 0.f;
    if (idx == 0) { g_bar_arrive = 0; g_bar_gen = 0; }
}

// ---------------- software grid barrier ----------------
__device__ __forceinline__ void gbar()
{
    __syncthreads();
    if (threadIdx.x == 0) {
        __threadfence();
        unsigned g = g_bar_gen;
        unsigned a = atomicAdd(&g_bar_arrive, 1);
        if (a == NCTA - 1) { g_bar_arrive = 0; __threadfence(); g_bar_gen = g + 1; }
        else while (g_bar_gen == g) __nanosleep(64);
    }
    __syncthreads();
}

// ---------------- persistent recurrent kernel ----------------
__global__ __launch_bounds__(256, 1) void lstm_steps(const float* __restrict__ c2c)
{
    extern __shared__ uint32_t smem[];
    const int cta = blockIdx.x;
    const int rb = (cta >> 5) * 64;        // batch rows
    const int nb = (cta & 31) * 128;       // packed gate cols
    const int tid = threadIdx.x, lane = tid & 31, wid = tid >> 5;
    const int wm = (wid >> 2) * 32, wn = (wid & 3) * 32;
    const int gq = lane >> 2, cc = lane & 3;
    const int r8 = tid >> 3, kq = tid & 7;
    const uint32_t sbase = (uint32_t)__cvta_generic_to_shared(smem);
    const float* Wb = g_Wxp + (size_t)nb * KD;   // chunks 0-31
    const float* Wh_ = g_Whp + (size_t)nb * KD;  // chunks 32-63

    int aoff[4], boff[4];
#pragma unroll
    for (int i = 0; i < 4; i++) aoff[i] = (wm + gq + i * 8) * LDSW + cc * 8;
#pragma unroll
    for (int i = 0; i < 4; i++) boff[i] = AS_W + (wn + gq + i * 8) * LDSW + cc * 8;

    for (int t = 0; t < TT; t++) {
        const float* xb = g_xp + ((size_t)t * BATCH + rb) * KD;
        const float* hb = g_hp[t & 1] + (size_t)rb * HID;
        float* hn = g_hp[(t + 1) & 1];

        float acc[2][4][4];
#pragma unroll
        for (int a = 0; a < 2; a++)
#pragma unroll
            for (int b = 0; b < 4; b++)
#pragma unroll
                for (int c = 0; c < 4; c++) acc[a][b][c] = 0.f;

        issue_tile(sbase, 0, xb, Wb, r8, kq);
        issue_tile(sbase, 1, xb + 32, Wb + 32, r8, kq);

        for (int kt = 0; kt < 64; kt++) {
            CP_WAIT1();
            __syncthreads();
            int tp = kt + 2;
            if (tp < 64) {
                const float* As_ = (tp < 32 ? xb : hb) + (tp & 31) * 32;
                const float* Bs_ = (tp < 32 ? Wb : Wh_) + (tp & 31) * 32;
                issue_tile(sbase, tp % 3, As_, Bs_, r8, kq);
            } else CP_COMMIT();
            compute_chunk(smem + (kt % 3) * STG, aoff, boff, acc);
        }

        // fused peephole gate update (even lane: gates i,f at col,col+1; odd: g,o)
#pragma unroll
        for (int mt = 0; mt < 2; mt++)
#pragma unroll
            for (int nt = 0; nt < 4; nt++) {
                int row0 = rb + wm + mt * 16 + gq;
                int col = nb + wn + nt * 8 + 2 * cc;
                float b0 = __ldg(g_biasp + col), b1 = __ldg(g_biasp + col + 1);
                float p0 = acc[mt][nt][0] + b0;
                float p1 = acc[mt][nt][1] + b1;
                float p2 = acc[mt][nt][2] + b0;
                float p3 = acc[mt][nt][3] + b1;
                float q0 = __shfl_xor_sync(~0u, p0, 1);
                float q1 = __shfl_xor_sync(~0u, p1, 1);
                float q2 = __shfl_xor_sync(~0u, p2, 1);
                float q3 = __shfl_xor_sync(~0u, p3, 1);
                if (!(lane & 1)) {
                    int j = col >> 2, pj = pdst(j);
                    float ciw = __ldg(c2c + j);
                    float cfw = __ldg(c2c + 1024 + j);
                    float cow = __ldg(c2c + 2048 + j);
                    {
                        float cold = g_c[row0 * HID + j];
                        float ig = sigf(p0 + ciw * cold);
                        float fg = sigf(p1 + cfw * cold);
                        float cn = fg * cold + ig * tanhf(q0);
                        float og = sigf(q1 + cow * cn);
                        g_c[row0 * HID + j] = cn;
                        hn[row0 * HID + pj] = __uint_as_float(f2t(og * tanhf(cn)));
                    }
                    {
                        int row1 = row0 + 8;
                        float cold = g_c[row1 * HID + j];
                        float ig = sigf(p2 + ciw * cold);
                        float fg = sigf(p3 + cfw * cold);
                        float cn = fg * cold + ig * tanhf(q2);
                        float og = sigf(q3 + cow * cn);
                        g_c[row1 * HID + j] = cn;
                        hn[row1 * HID + pj] = __uint_as_float(f2t(og * tanhf(cn)));
                    }
                }
            }
        gbar();
    }
}

// ---------------- final fc ----------------
__global__ __launch_bounds__(256, 1) void fc_gemm(
    const float* __restrict__ bfc, float* __restrict__ out)
{
    extern __shared__ uint32_t smem[];
    const int rb = blockIdx.y * 64;
    const int nb = blockIdx.x * 128;
    const int tid = threadIdx.x, lane = tid & 31, wid = tid >> 5;
    const int wm = (wid >> 2) * 32, wn = (wid & 3) * 32;
    const int gq = lane >> 2, cc = lane & 3;
    const int r8 = tid >> 3, kq = tid & 7;
    const uint32_t sbase = (uint32_t)__cvta_generic_to_shared(smem);
    const float* A = g_hp[0] + (size_t)rb * HID;   // final h (T even), permuted
    const float* Bw = g_Wfcp + (size_t)nb * KD;

    int aoff[4], boff[4];
#pragma unroll
    for (int i = 0; i < 4; i++) aoff[i] = (wm + gq + i * 8) * LDSW + cc * 8;
#pragma unroll
    for (int i = 0; i < 4; i++) boff[i] = AS_W + (wn + gq + i * 8) * LDSW + cc * 8;

    float acc[2][4][4];
#pragma unroll
    for (int a = 0; a < 2; a++)
#pragma unroll
        for (int b = 0; b < 4; b++)
#pragma unroll
            for (int c = 0; c < 4; c++) acc[a][b][c] = 0.f;

    issue_tile(sbase, 0, A, Bw, r8, kq);
    issue_tile(sbase, 1, A + 32, Bw + 32, r8, kq);

    for (int kt = 0; kt < 32; kt++) {
        CP_WAIT1();
        __syncthreads();
        int tp = kt + 2;
        if (tp < 32) issue_tile(sbase, tp % 3, A + tp * 32, Bw + tp * 32, r8, kq);
        else CP_COMMIT();
        compute_chunk(smem + (kt % 3) * STG, aoff, boff, acc);
    }

#pragma unroll
    for (int mt = 0; mt < 2; mt++)
#pragma unroll
        for (int nt = 0; nt < 4; nt++) {
            int col = nb + wn + nt * 8 + 2 * cc;
            float b0 = __ldg(bfc + col), b1 = __ldg(bfc + col + 1);
            int row0 = rb + wm + mt * 16 + gq;
            *(float2*)(out + (size_t)row0 * 1024 + col) =
                make_float2(acc[mt][nt][0] + b0, acc[mt][nt][1] + b1);
            *(float2*)(out + (size_t)(row0 + 8) * 1024 + col) =
                make_float2(acc[mt][nt][2] + b0, acc[mt][nt][3] + b1);
        }
}

// ---------------- launch ----------------
extern "C" void kernel_launch(void* const* d_in, const int* in_sizes, int n_in,
                              void* d_out, int out_size)
{
    const float* x   = (const float*)d_in[0];
    const float* Wx  = (const float*)d_in[1];
    const float* bx  = (const float*)d_in[2];
    const float* Wh  = (const float*)d_in[3];
    const float* bh  = (const float*)d_in[4];
    const float* c2c = (const float*)d_in[5];
    const float* Wfc = (const float*)d_in[6];
    const float* bfc = (const float*)d_in[7];
    float* out = (float*)d_out;

    cudaFuncSetAttribute(lstm_steps, cudaFuncAttributeMaxDynamicSharedMemorySize, SMEM_BYTES);
    cudaFuncSetAttribute(fc_gemm,    cudaFuncAttributeMaxDynamicSharedMemorySize, SMEM_BYTES);

    pack_w<<<NG + HID, 256>>>(Wx, Wh, bx, bh, Wfc);
    pack_x<<<BATCH * TT, 256>>>(x);
    init_kernel<<<1024, 256>>>();
    lstm_steps<<<NCTA, 256, SMEM_BYTES>>>(c2c);
    fc_gemm<<<dim3(8, 4), 256, SMEM_BYTES>>>(bfc, out);
}